// round 2
// baseline (speedup 1.0000x reference)
#include <cuda_runtime.h>
#include <cstdint>

// TriplaneDecoder: 2M points, 3x bilinear gather from 512x512x32 planes,
// feature product, MLP 32->64->64->4, sigmoid/exp + bounds mask.
// Output: [c (N*3 floats), sigma (N floats)] concatenated.

#define GRID_N   512
#define NF       32
#define HID      64
#define TPB      256

// ---- packed f32x2 helpers (bit-identical to scalar FMA, half the issue slots) ----
__device__ __forceinline__ unsigned long long pack2(float x, float y) {
    unsigned long long r;
    asm("mov.b64 %0, {%1,%2};" : "=l"(r) : "f"(x), "f"(y));
    return r;
}
__device__ __forceinline__ void unpack2(unsigned long long v, float& x, float& y) {
    asm("mov.b64 {%0,%1}, %2;" : "=f"(x), "=f"(y) : "l"(v));
}
#define FMA2(d, a, b, c) \
    asm("fma.rn.f32x2 %0, %1, %2, %3;" : "=l"(d) : "l"(a), "l"(b), "l"(c))

// Bilinear sample of 32-ch feature; FIRST writes feat[], else multiplies into it.
template<bool FIRST>
__device__ __forceinline__ void bilerp_mul(const float* __restrict__ plane,
                                           float cu, float cv, float* feat) {
    const float S = 0.5f * (float)(GRID_N - 1);
    float u = fminf(fmaxf((cu + 1.0f) * S, 0.0f), (float)(GRID_N - 1));
    float v = fminf(fmaxf((cv + 1.0f) * S, 0.0f), (float)(GRID_N - 1));
    float fu = floorf(u), fv = floorf(v);
    int u0 = (int)fu, v0 = (int)fv;
    int u1 = min(u0 + 1, GRID_N - 1);
    int v1 = min(v0 + 1, GRID_N - 1);
    float wu = u - fu, wv = v - fv;
    float w00 = (1.0f - wu) * (1.0f - wv);
    float w01 = (1.0f - wu) * wv;
    float w10 = wu * (1.0f - wv);
    float w11 = wu * wv;

    const float4* p00 = (const float4*)(plane + ((u0 * GRID_N + v0) * NF));
    const float4* p01 = (const float4*)(plane + ((u0 * GRID_N + v1) * NF));
    const float4* p10 = (const float4*)(plane + ((u1 * GRID_N + v0) * NF));
    const float4* p11 = (const float4*)(plane + ((u1 * GRID_N + v1) * NF));

    #pragma unroll
    for (int q = 0; q < NF / 4; q++) {
        float4 a = __ldg(p00 + q);
        float4 b = __ldg(p01 + q);
        float4 c = __ldg(p10 + q);
        float4 d = __ldg(p11 + q);
        float rx = fmaf(d.x, w11, fmaf(c.x, w10, fmaf(b.x, w01, a.x * w00)));
        float ry = fmaf(d.y, w11, fmaf(c.y, w10, fmaf(b.y, w01, a.y * w00)));
        float rz = fmaf(d.z, w11, fmaf(c.z, w10, fmaf(b.z, w01, a.z * w00)));
        float rw = fmaf(d.w, w11, fmaf(c.w, w10, fmaf(b.w, w01, a.w * w00)));
        if (FIRST) {
            feat[4*q+0] = rx; feat[4*q+1] = ry; feat[4*q+2] = rz; feat[4*q+3] = rw;
        } else {
            feat[4*q+0] *= rx; feat[4*q+1] *= ry; feat[4*q+2] *= rz; feat[4*q+3] *= rw;
        }
    }
}

__global__ __launch_bounds__(TPB)
void triplane_decoder_kernel(const float* __restrict__ x,
                             const float* __restrict__ pzh,
                             const float* __restrict__ phw,
                             const float* __restrict__ pzw,
                             const float* __restrict__ W1,
                             const float* __restrict__ W2,
                             const float* __restrict__ W3,
                             float* __restrict__ out, int n) {
    __shared__ __align__(16) float sW1[NF * HID];    //  8 KB
    __shared__ __align__(16) float sW2[HID * HID];   // 16 KB
    __shared__ __align__(16) float sW3[HID * 4];     //  1 KB

    int tid = threadIdx.x;
    for (int i = tid; i < NF * HID;  i += TPB) sW1[i] = W1[i];
    for (int i = tid; i < HID * HID; i += TPB) sW2[i] = W2[i];
    for (int i = tid; i < HID * 4;   i += TPB) sW3[i] = W3[i];
    __syncthreads();

    int i = blockIdx.x * TPB + tid;
    if (i >= n) return;

    float x0 = x[3 * i + 0];
    float x1 = x[3 * i + 1];
    float x2 = x[3 * i + 2];
    bool mask = (fabsf(x0) < 1.0f) && (fabsf(x1) < 1.0f) && (fabsf(x2) < 1.0f);

    // ---- triplane gather: features = F_zh * F_hw * F_zw ----
    float feat[NF];
    bilerp_mul<true >(pzh, x0, x1, feat);   // plane_zh, uv=(z,h)
    bilerp_mul<false>(phw, x1, x2, feat);   // plane_hw, uv=(h,w)
    bilerp_mul<false>(pzw, x2, x0, feat);   // plane_zw, uv=(w,z)

    // ---- Layer 1: h1 = relu(feat @ W1), h1 held as 32 packed f32x2 ----
    unsigned long long H1[HID / 2];
    #pragma unroll
    for (int j = 0; j < HID / 2; j++) H1[j] = 0ULL;
    #pragma unroll
    for (int f = 0; f < NF; f++) {
        unsigned long long aa = pack2(feat[f], feat[f]);
        const unsigned long long* w =
            reinterpret_cast<const unsigned long long*>(sW1 + f * HID);
        #pragma unroll
        for (int j = 0; j < HID / 2; j++) FMA2(H1[j], aa, w[j], H1[j]);
    }
    #pragma unroll
    for (int j = 0; j < HID / 2; j++) {
        float a, b; unpack2(H1[j], a, b);
        H1[j] = pack2(fmaxf(a, 0.0f), fmaxf(b, 0.0f));
    }

    // ---- Layer 2 (chunks of 16 outputs) fused with Layer 3 ----
    float o0 = 0.0f, o1 = 0.0f, o2 = 0.0f, o3 = 0.0f;
    #pragma unroll
    for (int c = 0; c < 4; c++) {
        unsigned long long H2[8];
        #pragma unroll
        for (int j = 0; j < 8; j++) H2[j] = 0ULL;
        #pragma unroll
        for (int k2 = 0; k2 < HID / 2; k2++) {
            float a, b; unpack2(H1[k2], a, b);
            unsigned long long aa = pack2(a, a);
            unsigned long long bb = pack2(b, b);
            const unsigned long long* wA =
                reinterpret_cast<const unsigned long long*>(sW2 + (2 * k2 + 0) * HID + c * 16);
            const unsigned long long* wB =
                reinterpret_cast<const unsigned long long*>(sW2 + (2 * k2 + 1) * HID + c * 16);
            #pragma unroll
            for (int j = 0; j < 8; j++) FMA2(H2[j], aa, wA[j], H2[j]);
            #pragma unroll
            for (int j = 0; j < 8; j++) FMA2(H2[j], bb, wB[j], H2[j]);
        }
        // relu + layer 3 accumulation for these 16 hidden units
        #pragma unroll
        for (int j = 0; j < 8; j++) {
            float a, b; unpack2(H2[j], a, b);
            a = fmaxf(a, 0.0f); b = fmaxf(b, 0.0f);
            int k0 = c * 16 + 2 * j;
            o0 = fmaf(a, sW3[k0 * 4 + 0], o0);
            o1 = fmaf(a, sW3[k0 * 4 + 1], o1);
            o2 = fmaf(a, sW3[k0 * 4 + 2], o2);
            o3 = fmaf(a, sW3[k0 * 4 + 3], o3);
            o0 = fmaf(b, sW3[(k0 + 1) * 4 + 0], o0);
            o1 = fmaf(b, sW3[(k0 + 1) * 4 + 1], o1);
            o2 = fmaf(b, sW3[(k0 + 1) * 4 + 2], o2);
            o3 = fmaf(b, sW3[(k0 + 1) * 4 + 3], o3);
        }
    }

    // ---- activations + masked write ----
    float c0 = mask ? 1.0f / (1.0f + __expf(-o0)) : 0.0f;
    float c1 = mask ? 1.0f / (1.0f + __expf(-o1)) : 0.0f;
    float c2 = mask ? 1.0f / (1.0f + __expf(-o2)) : 0.0f;
    float sg = mask ? __expf(o3) : 0.0f;

    out[3 * i + 0] = c0;
    out[3 * i + 1] = c1;
    out[3 * i + 2] = c2;
    out[3 * n + i] = sg;
}

extern "C" void kernel_launch(void* const* d_in, const int* in_sizes, int n_in,
                              void* d_out, int out_size) {
    const float* x   = (const float*)d_in[0];  // [N,3]
    const float* pzh = (const float*)d_in[1];  // [512,512,32]
    const float* phw = (const float*)d_in[2];
    const float* pzw = (const float*)d_in[3];
    const float* W1  = (const float*)d_in[4];  // [32,64]
    const float* W2  = (const float*)d_in[5];  // [64,64]
    const float* W3  = (const float*)d_in[6];  // [64,4]
    float* out = (float*)d_out;

    int n = in_sizes[0] / 3;
    int blocks = (n + TPB - 1) / TPB;
    triplane_decoder_kernel<<<blocks, TPB>>>(x, pzh, phw, pzw, W1, W2, W3, out, n);
}

// round 4
// speedup vs baseline: 1.1813x; 1.1813x over previous
#include <cuda_runtime.h>
#include <cstdint>

// TriplaneDecoder: 2M points, 3x bilinear gather from 512x512x32 planes,
// feature product, MLP 32->64->64->4, sigmoid/exp + bounds mask.
// Output: [c (N*3 floats), sigma (N floats)] concatenated.

#define GRID_N   512
#define NF       32
#define HID      64
#define TPB      256

typedef unsigned long long u64;

// ---- packed f32x2 helpers ----
__device__ __forceinline__ u64 pack2(float x, float y) {
    u64 r; asm("mov.b64 %0, {%1,%2};" : "=l"(r) : "f"(x), "f"(y)); return r;
}
__device__ __forceinline__ void unpack2(u64 v, float& x, float& y) {
    asm("mov.b64 {%0,%1}, %2;" : "=f"(x), "=f"(y) : "l"(v));
}
#define FMA2(d, a, b, c) \
    asm("fma.rn.f32x2 %0, %1, %2, %3;" : "=l"(d) : "l"(a), "l"(b), "l"(c))
#define MUL2(d, a, b) \
    asm("mul.rn.f32x2 %0, %1, %2;" : "=l"(d) : "l"(a), "l"(b))

__global__ __launch_bounds__(TPB, 2)
void triplane_decoder_kernel(const float* __restrict__ x,
                             const float* __restrict__ pzh,
                             const float* __restrict__ phw,
                             const float* __restrict__ pzw,
                             const float* __restrict__ W1,
                             const float* __restrict__ W2,
                             const float* __restrict__ W3,
                             float* __restrict__ out, int n) {
    __shared__ __align__(16) float sW1[NF * HID];    //  8 KB
    __shared__ __align__(16) float sW2[HID * HID];   // 16 KB
    __shared__ __align__(16) float sW3[HID * 4];     //  1 KB

    int tid = threadIdx.x;
    for (int k = tid; k < NF * HID;  k += TPB) sW1[k] = W1[k];
    for (int k = tid; k < HID * HID; k += TPB) sW2[k] = W2[k];
    for (int k = tid; k < HID * 4;   k += TPB) sW3[k] = W3[k];
    __syncthreads();

    int i = blockIdx.x * TPB + tid;
    if (i >= n) return;

    float x0 = x[3 * i + 0];
    float x1 = x[3 * i + 1];
    float x2 = x[3 * i + 2];
    bool mask = (fabsf(x0) < 1.0f) && (fabsf(x1) < 1.0f) && (fabsf(x2) < 1.0f);

    // ---- per-plane bilerp setup: 4 corner pointers + packed broadcast weights ----
    const float* planes[3] = {pzh, phw, pzw};
    float cus[3] = {x0, x1, x2};
    float cvs[3] = {x1, x2, x0};

    const ulonglong2* P[3][4];
    u64 WQ[3][4];
    #pragma unroll
    for (int p = 0; p < 3; p++) {
        const float S = 0.5f * (float)(GRID_N - 1);
        float u = fminf(fmaxf(fmaf(cus[p], S, S), 0.0f), (float)(GRID_N - 1));
        float v = fminf(fmaxf(fmaf(cvs[p], S, S), 0.0f), (float)(GRID_N - 1));
        float fu = floorf(u), fv = floorf(v);
        int u0 = (int)fu, v0 = (int)fv;
        int u1 = min(u0 + 1, GRID_N - 1);
        int v1 = min(v0 + 1, GRID_N - 1);
        float wu = u - fu, wv = v - fv;
        float w00 = (1.0f - wu) * (1.0f - wv);
        float w01 = (1.0f - wu) * wv;
        float w10 = wu * (1.0f - wv);
        float w11 = wu * wv;
        WQ[p][0] = pack2(w00, w00);
        WQ[p][1] = pack2(w01, w01);
        WQ[p][2] = pack2(w10, w10);
        WQ[p][3] = pack2(w11, w11);
        P[p][0] = (const ulonglong2*)(planes[p] + (u0 * GRID_N + v0) * NF);
        P[p][1] = (const ulonglong2*)(planes[p] + (u0 * GRID_N + v1) * NF);
        P[p][2] = (const ulonglong2*)(planes[p] + (u1 * GRID_N + v0) * NF);
        P[p][3] = (const ulonglong2*)(planes[p] + (u1 * GRID_N + v1) * NF);
    }

    // ---- gather fused with Layer 1 (h1 accumulated in 32 packed pairs) ----
    u64 H1[HID / 2];
    #pragma unroll
    for (int j = 0; j < HID / 2; j++) H1[j] = 0ULL;

    #pragma unroll
    for (int q = 0; q < NF / 4; q++) {   // 4 channels per chunk
        u64 flo = 0ULL, fhi = 0ULL;
        #pragma unroll
        for (int p = 0; p < 3; p++) {
            ulonglong2 A = P[p][0][q];
            ulonglong2 B = P[p][1][q];
            ulonglong2 C = P[p][2][q];
            ulonglong2 D = P[p][3][q];
            u64 rlo, rhi;
            MUL2(rlo, A.x, WQ[p][0]);
            FMA2(rlo, B.x, WQ[p][1], rlo);
            FMA2(rlo, C.x, WQ[p][2], rlo);
            FMA2(rlo, D.x, WQ[p][3], rlo);
            MUL2(rhi, A.y, WQ[p][0]);
            FMA2(rhi, B.y, WQ[p][1], rhi);
            FMA2(rhi, C.y, WQ[p][2], rhi);
            FMA2(rhi, D.y, WQ[p][3], rhi);
            if (p == 0) { flo = rlo; fhi = rhi; }
            else        { MUL2(flo, flo, rlo); MUL2(fhi, fhi, rhi); }
        }
        float f0, f1, f2, f3;
        unpack2(flo, f0, f1);
        unpack2(fhi, f2, f3);
        float fc[4] = {f0, f1, f2, f3};
        #pragma unroll
        for (int c = 0; c < 4; c++) {
            u64 aa = pack2(fc[c], fc[c]);
            const ulonglong2* wr = (const ulonglong2*)(sW1 + (4 * q + c) * HID);
            #pragma unroll
            for (int j = 0; j < 16; j++) {
                ulonglong2 wv = wr[j];
                FMA2(H1[2 * j + 0], aa, wv.x, H1[2 * j + 0]);
                FMA2(H1[2 * j + 1], aa, wv.y, H1[2 * j + 1]);
            }
        }
    }

    // relu on h1 (stored back as packed pairs)
    #pragma unroll
    for (int j = 0; j < HID / 2; j++) {
        float a, b; unpack2(H1[j], a, b);
        H1[j] = pack2(fmaxf(a, 0.0f), fmaxf(b, 0.0f));
    }

    // ---- Layer 2 (chunks of 16 outputs) fused with Layer 3 ----
    u64 o01 = 0ULL, o23 = 0ULL;
    #pragma unroll
    for (int cc = 0; cc < 4; cc++) {
        u64 H2[8];
        #pragma unroll
        for (int j = 0; j < 8; j++) H2[j] = 0ULL;
        #pragma unroll
        for (int k = 0; k < HID / 2; k++) {
            float a, b; unpack2(H1[k], a, b);
            u64 aa = pack2(a, a);
            u64 bb = pack2(b, b);
            const ulonglong2* wA = (const ulonglong2*)(sW2 + (2 * k + 0) * HID + cc * 16);
            const ulonglong2* wB = (const ulonglong2*)(sW2 + (2 * k + 1) * HID + cc * 16);
            #pragma unroll
            for (int j = 0; j < 4; j++) {
                ulonglong2 wv = wA[j];
                FMA2(H2[2 * j + 0], aa, wv.x, H2[2 * j + 0]);
                FMA2(H2[2 * j + 1], aa, wv.y, H2[2 * j + 1]);
            }
            #pragma unroll
            for (int j = 0; j < 4; j++) {
                ulonglong2 wv = wB[j];
                FMA2(H2[2 * j + 0], bb, wv.x, H2[2 * j + 0]);
                FMA2(H2[2 * j + 1], bb, wv.y, H2[2 * j + 1]);
            }
        }
        // relu + Layer 3 accumulation (packed output pairs)
        #pragma unroll
        for (int j = 0; j < 8; j++) {
            float a, b; unpack2(H2[j], a, b);
            a = fmaxf(a, 0.0f); b = fmaxf(b, 0.0f);
            int k0 = cc * 16 + 2 * j;
            const ulonglong2* w3 = (const ulonglong2*)(sW3 + k0 * 4);
            ulonglong2 wa = w3[0];
            ulonglong2 wb = w3[1];
            u64 aa = pack2(a, a);
            u64 bb = pack2(b, b);
            FMA2(o01, aa, wa.x, o01);
            FMA2(o23, aa, wa.y, o23);
            FMA2(o01, bb, wb.x, o01);
            FMA2(o23, bb, wb.y, o23);
        }
    }
    float o0, o1, o2, o3;
    unpack2(o01, o0, o1);
    unpack2(o23, o2, o3);

    // ---- activations + masked write ----
    float c0 = mask ? 1.0f / (1.0f + __expf(-o0)) : 0.0f;
    float c1 = mask ? 1.0f / (1.0f + __expf(-o1)) : 0.0f;
    float c2 = mask ? 1.0f / (1.0f + __expf(-o2)) : 0.0f;
    float sg = mask ? __expf(o3) : 0.0f;

    out[3 * i + 0] = c0;
    out[3 * i + 1] = c1;
    out[3 * i + 2] = c2;
    out[3 * n + i] = sg;
}

extern "C" void kernel_launch(void* const* d_in, const int* in_sizes, int n_in,
                              void* d_out, int out_size) {
    const float* x   = (const float*)d_in[0];  // [N,3]
    const float* pzh = (const float*)d_in[1];  // [512,512,32]
    const float* phw = (const float*)d_in[2];
    const float* pzw = (const float*)d_in[3];
    const float* W1  = (const float*)d_in[4];  // [32,64]
    const float* W2  = (const float*)d_in[5];  // [64,64]
    const float* W3  = (const float*)d_in[6];  // [64,4]
    float* out = (float*)d_out;

    int n = in_sizes[0] / 3;
    int blocks = (n + TPB - 1) / TPB;
    triplane_decoder_kernel<<<blocks, TPB>>>(x, pzh, phw, pzw, W1, W2, W3, out, n);
}

// round 5
// speedup vs baseline: 1.8608x; 1.5753x over previous
#include <cuda_runtime.h>
#include <cstdint>

// TriplaneDecoder: 2M points, 3x bilinear gather from 512x512x32 planes,
// feature product, MLP 32->64->64->4, sigmoid/exp + bounds mask.
// Output: [c (N*3 floats), sigma (N floats)] concatenated.
//
// R4: warp-cooperative coalesced gather (8 lanes per 128B corner row),
// features staged in padded SMEM tile, MLP unchanged (packed f32x2).

#define GRID_N   512
#define NF       32
#define HID      64
#define TPB      256
#define FSTR     36            // feature row stride in floats (padded, 16B aligned)
#define FULLMASK 0xffffffffu

typedef unsigned long long u64;

__device__ __forceinline__ u64 pack2(float x, float y) {
    u64 r; asm("mov.b64 %0, {%1,%2};" : "=l"(r) : "f"(x), "f"(y)); return r;
}
__device__ __forceinline__ void unpack2(u64 v, float& x, float& y) {
    asm("mov.b64 {%0,%1}, %2;" : "=f"(x), "=f"(y) : "l"(v));
}
#define FMA2(d, a, b, c) \
    asm("fma.rn.f32x2 %0, %1, %2, %3;" : "=l"(d) : "l"(a), "l"(b), "l"(c))
#define MUL2(d, a, b) \
    asm("mul.rn.f32x2 %0, %1, %2;" : "=l"(d) : "l"(a), "l"(b))

extern __shared__ float smemDyn[];
// layout: sW1[2048] | sW2[4096] | sW3[256] | feat[8 warps * 32 * FSTR]

__global__ __launch_bounds__(TPB, 2)
void triplane_decoder_kernel(const float* __restrict__ x,
                             const float* __restrict__ pzh,
                             const float* __restrict__ phw,
                             const float* __restrict__ pzw,
                             const float* __restrict__ W1,
                             const float* __restrict__ W2,
                             const float* __restrict__ W3,
                             float* __restrict__ out, int n) {
    float* sW1  = smemDyn;
    float* sW2  = sW1 + NF * HID;
    float* sW3  = sW2 + HID * HID;
    float* sFeat = sW3 + HID * 4;

    int tid = threadIdx.x;
    for (int k = tid; k < NF * HID;  k += TPB) sW1[k] = W1[k];
    for (int k = tid; k < HID * HID; k += TPB) sW2[k] = W2[k];
    for (int k = tid; k < HID * 4;   k += TPB) sW3[k] = W3[k];
    __syncthreads();

    int lane = tid & 31;
    int warp = tid >> 5;
    int i0 = blockIdx.x * TPB + tid;
    int i = min(i0, n - 1);               // clamp so all lanes participate

    float x0 = x[3 * i + 0];
    float x1 = x[3 * i + 1];
    float x2 = x[3 * i + 2];
    bool mask = (fabsf(x0) < 1.0f) && (fabsf(x1) < 1.0f) && (fabsf(x2) < 1.0f);

    // ---- per-point setup: 12 corner offsets (float4 units) + 12 weights ----
    float cus[3] = {x0, x1, x2};
    float cvs[3] = {x1, x2, x0};
    unsigned off4[3][4];
    float    wgt[3][4];
    #pragma unroll
    for (int p = 0; p < 3; p++) {
        const float S = 0.5f * (float)(GRID_N - 1);
        float u = fminf(fmaxf(fmaf(cus[p], S, S), 0.0f), (float)(GRID_N - 1));
        float v = fminf(fmaxf(fmaf(cvs[p], S, S), 0.0f), (float)(GRID_N - 1));
        float fu = floorf(u), fv = floorf(v);
        int u0 = (int)fu, v0 = (int)fv;
        int u1 = min(u0 + 1, GRID_N - 1);
        int v1 = min(v0 + 1, GRID_N - 1);
        float wu = u - fu, wv = v - fv;
        wgt[p][0] = (1.0f - wu) * (1.0f - wv);
        wgt[p][1] = (1.0f - wu) * wv;
        wgt[p][2] = wu * (1.0f - wv);
        wgt[p][3] = wu * wv;
        off4[p][0] = (unsigned)((u0 * GRID_N + v0) * (NF / 4));
        off4[p][1] = (unsigned)((u0 * GRID_N + v1) * (NF / 4));
        off4[p][2] = (unsigned)((u1 * GRID_N + v0) * (NF / 4));
        off4[p][3] = (unsigned)((u1 * GRID_N + v1) * (NF / 4));
    }

    // ---- warp-cooperative coalesced gather + interpolation ----
    // pass t: points (warp-local) 4t..4t+3; lanes 8j+k serve point 4t+j chunk k.
    const float4* bases[3] = {(const float4*)pzh, (const float4*)phw, (const float4*)pzw};
    float* fWarp = sFeat + warp * 32 * FSTR;
    int j = lane >> 3;
    int k = lane & 7;

    #pragma unroll
    for (int t = 0; t < 8; t++) {
        int src = 4 * t + j;
        float4 acc;
        #pragma unroll
        for (int p = 0; p < 3; p++) {
            float4 pf;
            #pragma unroll
            for (int c = 0; c < 4; c++) {
                unsigned o = __shfl_sync(FULLMASK, off4[p][c], src);
                float    w = __shfl_sync(FULLMASK, wgt[p][c], src);
                float4 d = __ldg(bases[p] + o + k);
                if (c == 0) {
                    pf.x = w * d.x; pf.y = w * d.y; pf.z = w * d.z; pf.w = w * d.w;
                } else {
                    pf.x = fmaf(w, d.x, pf.x); pf.y = fmaf(w, d.y, pf.y);
                    pf.z = fmaf(w, d.z, pf.z); pf.w = fmaf(w, d.w, pf.w);
                }
            }
            if (p == 0) acc = pf;
            else { acc.x *= pf.x; acc.y *= pf.y; acc.z *= pf.z; acc.w *= pf.w; }
        }
        *(float4*)(fWarp + src * FSTR + k * 4) = acc;
    }
    __syncwarp();

    // ---- read back own features ----
    float feat[NF];
    const float* myRow = fWarp + lane * FSTR;
    #pragma unroll
    for (int q = 0; q < NF / 4; q++) {
        float4 v = *(const float4*)(myRow + 4 * q);
        feat[4 * q + 0] = v.x; feat[4 * q + 1] = v.y;
        feat[4 * q + 2] = v.z; feat[4 * q + 3] = v.w;
    }

    // ---- Layer 1: h1 = relu(feat @ W1), accumulated as 32 packed pairs ----
    u64 H1[HID / 2];
    #pragma unroll
    for (int jj = 0; jj < HID / 2; jj++) H1[jj] = 0ULL;
    #pragma unroll
    for (int f = 0; f < NF; f++) {
        u64 aa = pack2(feat[f], feat[f]);
        const ulonglong2* wr = (const ulonglong2*)(sW1 + f * HID);
        #pragma unroll
        for (int jj = 0; jj < 16; jj++) {
            ulonglong2 wv = wr[jj];
            FMA2(H1[2 * jj + 0], aa, wv.x, H1[2 * jj + 0]);
            FMA2(H1[2 * jj + 1], aa, wv.y, H1[2 * jj + 1]);
        }
    }
    #pragma unroll
    for (int jj = 0; jj < HID / 2; jj++) {
        float a, b; unpack2(H1[jj], a, b);
        H1[jj] = pack2(fmaxf(a, 0.0f), fmaxf(b, 0.0f));
    }

    // ---- Layer 2 (chunks of 16 outputs) fused with Layer 3 ----
    u64 o01 = 0ULL, o23 = 0ULL;
    #pragma unroll
    for (int cc = 0; cc < 4; cc++) {
        u64 H2[8];
        #pragma unroll
        for (int jj = 0; jj < 8; jj++) H2[jj] = 0ULL;
        #pragma unroll
        for (int kk = 0; kk < HID / 2; kk++) {
            float a, b; unpack2(H1[kk], a, b);
            u64 aa = pack2(a, a);
            u64 bb = pack2(b, b);
            const ulonglong2* wA = (const ulonglong2*)(sW2 + (2 * kk + 0) * HID + cc * 16);
            const ulonglong2* wB = (const ulonglong2*)(sW2 + (2 * kk + 1) * HID + cc * 16);
            #pragma unroll
            for (int jj = 0; jj < 4; jj++) {
                ulonglong2 wv = wA[jj];
                FMA2(H2[2 * jj + 0], aa, wv.x, H2[2 * jj + 0]);
                FMA2(H2[2 * jj + 1], aa, wv.y, H2[2 * jj + 1]);
            }
            #pragma unroll
            for (int jj = 0; jj < 4; jj++) {
                ulonglong2 wv = wB[jj];
                FMA2(H2[2 * jj + 0], bb, wv.x, H2[2 * jj + 0]);
                FMA2(H2[2 * jj + 1], bb, wv.y, H2[2 * jj + 1]);
            }
        }
        #pragma unroll
        for (int jj = 0; jj < 8; jj++) {
            float a, b; unpack2(H2[jj], a, b);
            a = fmaxf(a, 0.0f); b = fmaxf(b, 0.0f);
            int k0 = cc * 16 + 2 * jj;
            const ulonglong2* w3 = (const ulonglong2*)(sW3 + k0 * 4);
            ulonglong2 wa = w3[0];
            ulonglong2 wb = w3[1];
            u64 aa = pack2(a, a);
            u64 bb = pack2(b, b);
            FMA2(o01, aa, wa.x, o01);
            FMA2(o23, aa, wa.y, o23);
            FMA2(o01, bb, wb.x, o01);
            FMA2(o23, bb, wb.y, o23);
        }
    }
    float o0, o1, o2, o3;
    unpack2(o01, o0, o1);
    unpack2(o23, o2, o3);

    // ---- activations + masked write ----
    if (i0 < n) {
        float c0 = mask ? 1.0f / (1.0f + __expf(-o0)) : 0.0f;
        float c1 = mask ? 1.0f / (1.0f + __expf(-o1)) : 0.0f;
        float c2 = mask ? 1.0f / (1.0f + __expf(-o2)) : 0.0f;
        float sg = mask ? __expf(o3) : 0.0f;
        out[3 * i0 + 0] = c0;
        out[3 * i0 + 1] = c1;
        out[3 * i0 + 2] = c2;
        out[3 * n + i0] = sg;
    }
}

extern "C" void kernel_launch(void* const* d_in, const int* in_sizes, int n_in,
                              void* d_out, int out_size) {
    const float* x   = (const float*)d_in[0];  // [N,3]
    const float* pzh = (const float*)d_in[1];  // [512,512,32]
    const float* phw = (const float*)d_in[2];
    const float* pzw = (const float*)d_in[3];
    const float* W1  = (const float*)d_in[4];  // [32,64]
    const float* W2  = (const float*)d_in[5];  // [64,64]
    const float* W3  = (const float*)d_in[6];  // [64,4]
    float* out = (float*)d_out;

    int n = in_sizes[0] / 3;
    int blocks = (n + TPB - 1) / TPB;

    size_t smem = (size_t)(NF * HID + HID * HID + HID * 4 + 8 * 32 * FSTR) * sizeof(float);
    cudaFuncSetAttribute(triplane_decoder_kernel,
                         cudaFuncAttributeMaxDynamicSharedMemorySize, (int)smem);
    triplane_decoder_kernel<<<blocks, TPB, smem>>>(x, pzh, phw, pzw, W1, W2, W3, out, n);
}

// round 8
// speedup vs baseline: 2.3928x; 1.2859x over previous
#include <cuda_runtime.h>
#include <cstdint>

// TriplaneDecoder: 2M points, 3x bilinear gather from 512x512x32 planes,
// feature product, MLP 32->64->64->4, sigmoid/exp + bounds mask.
// Output: [c (N*3 floats), sigma (N floats)] concatenated.
//
// R6 (= R5 resubmit after infra failure): weights in __constant__ memory
// (LDCU uniform port, off the L1 crossbar); warp-cooperative coalesced
// gather; MLP packed f32x2.

#define GRID_N   512
#define NF       32
#define HID      64
#define TPB      256
#define FSTR     36            // feature row stride in floats (padded, 16B aligned)
#define FULLMASK 0xffffffffu

typedef unsigned long long u64;

__constant__ float cW1[NF * HID];    //  8 KB
__constant__ float cW2[HID * HID];   // 16 KB
__constant__ float cW3[HID * 4];     //  1 KB

__device__ __forceinline__ u64 pack2(float x, float y) {
    u64 r; asm("mov.b64 %0, {%1,%2};" : "=l"(r) : "f"(x), "f"(y)); return r;
}
__device__ __forceinline__ void unpack2(u64 v, float& x, float& y) {
    asm("mov.b64 {%0,%1}, %2;" : "=f"(x), "=f"(y) : "l"(v));
}
#define FMA2(d, a, b, c) \
    asm("fma.rn.f32x2 %0, %1, %2, %3;" : "=l"(d) : "l"(a), "l"(b), "l"(c))

extern __shared__ float smemDyn[];   // feat tile: 8 warps * 32 * FSTR floats

__global__ __launch_bounds__(TPB, 2)
void triplane_decoder_kernel(const float* __restrict__ x,
                             const float* __restrict__ pzh,
                             const float* __restrict__ phw,
                             const float* __restrict__ pzw,
                             float* __restrict__ out, int n) {
    float* sFeat = smemDyn;

    int tid  = threadIdx.x;
    int lane = tid & 31;
    int warp = tid >> 5;
    int i0 = blockIdx.x * TPB + tid;
    int i = min(i0, n - 1);               // clamp so all lanes participate

    float x0 = x[3 * i + 0];
    float x1 = x[3 * i + 1];
    float x2 = x[3 * i + 2];
    bool mask = (fabsf(x0) < 1.0f) && (fabsf(x1) < 1.0f) && (fabsf(x2) < 1.0f);

    // ---- per-point setup: 12 corner offsets (float4 units) + 12 weights ----
    float cus[3] = {x0, x1, x2};
    float cvs[3] = {x1, x2, x0};
    unsigned off4[3][4];
    float    wgt[3][4];
    #pragma unroll
    for (int p = 0; p < 3; p++) {
        const float S = 0.5f * (float)(GRID_N - 1);
        float u = fminf(fmaxf(fmaf(cus[p], S, S), 0.0f), (float)(GRID_N - 1));
        float v = fminf(fmaxf(fmaf(cvs[p], S, S), 0.0f), (float)(GRID_N - 1));
        float fu = floorf(u), fv = floorf(v);
        int u0 = (int)fu, v0 = (int)fv;
        int u1 = min(u0 + 1, GRID_N - 1);
        int v1 = min(v0 + 1, GRID_N - 1);
        float wu = u - fu, wv = v - fv;
        wgt[p][0] = (1.0f - wu) * (1.0f - wv);
        wgt[p][1] = (1.0f - wu) * wv;
        wgt[p][2] = wu * (1.0f - wv);
        wgt[p][3] = wu * wv;
        off4[p][0] = (unsigned)((u0 * GRID_N + v0) * (NF / 4));
        off4[p][1] = (unsigned)((u0 * GRID_N + v1) * (NF / 4));
        off4[p][2] = (unsigned)((u1 * GRID_N + v0) * (NF / 4));
        off4[p][3] = (unsigned)((u1 * GRID_N + v1) * (NF / 4));
    }

    // ---- warp-cooperative coalesced gather + interpolation ----
    // pass t: points (warp-local) 4t..4t+3; lanes 8j+k serve point 4t+j chunk k.
    const float4* bases[3] = {(const float4*)pzh, (const float4*)phw, (const float4*)pzw};
    float* fWarp = sFeat + warp * 32 * FSTR;
    int j = lane >> 3;
    int k = lane & 7;

    #pragma unroll
    for (int t = 0; t < 8; t++) {
        int src = 4 * t + j;
        float4 acc;
        #pragma unroll
        for (int p = 0; p < 3; p++) {
            float4 pf;
            #pragma unroll
            for (int c = 0; c < 4; c++) {
                unsigned o = __shfl_sync(FULLMASK, off4[p][c], src);
                float    w = __shfl_sync(FULLMASK, wgt[p][c], src);
                float4 d = __ldg(bases[p] + o + k);
                if (c == 0) {
                    pf.x = w * d.x; pf.y = w * d.y; pf.z = w * d.z; pf.w = w * d.w;
                } else {
                    pf.x = fmaf(w, d.x, pf.x); pf.y = fmaf(w, d.y, pf.y);
                    pf.z = fmaf(w, d.z, pf.z); pf.w = fmaf(w, d.w, pf.w);
                }
            }
            if (p == 0) acc = pf;
            else { acc.x *= pf.x; acc.y *= pf.y; acc.z *= pf.z; acc.w *= pf.w; }
        }
        *(float4*)(fWarp + src * FSTR + k * 4) = acc;
    }
    __syncwarp();

    // ---- read back own features ----
    float feat[NF];
    const float* myRow = fWarp + lane * FSTR;
    #pragma unroll
    for (int q = 0; q < NF / 4; q++) {
        float4 v = *(const float4*)(myRow + 4 * q);
        feat[4 * q + 0] = v.x; feat[4 * q + 1] = v.y;
        feat[4 * q + 2] = v.z; feat[4 * q + 3] = v.w;
    }

    // ---- Layer 1: h1 = relu(feat @ W1), accumulated as 32 packed pairs ----
    u64 H1[HID / 2];
    #pragma unroll
    for (int jj = 0; jj < HID / 2; jj++) H1[jj] = 0ULL;
    #pragma unroll
    for (int f = 0; f < NF; f++) {
        u64 aa = pack2(feat[f], feat[f]);
        const ulonglong2* wr = (const ulonglong2*)(cW1 + f * HID);
        #pragma unroll
        for (int jj = 0; jj < 16; jj++) {
            ulonglong2 wv = wr[jj];
            FMA2(H1[2 * jj + 0], aa, wv.x, H1[2 * jj + 0]);
            FMA2(H1[2 * jj + 1], aa, wv.y, H1[2 * jj + 1]);
        }
    }
    #pragma unroll
    for (int jj = 0; jj < HID / 2; jj++) {
        float a, b; unpack2(H1[jj], a, b);
        H1[jj] = pack2(fmaxf(a, 0.0f), fmaxf(b, 0.0f));
    }

    // ---- Layer 2 (chunks of 16 outputs) fused with Layer 3 ----
    u64 o01 = 0ULL, o23 = 0ULL;
    #pragma unroll
    for (int cc = 0; cc < 4; cc++) {
        u64 H2[8];
        #pragma unroll
        for (int jj = 0; jj < 8; jj++) H2[jj] = 0ULL;
        #pragma unroll
        for (int kk = 0; kk < HID / 2; kk++) {
            float a, b; unpack2(H1[kk], a, b);
            u64 aa = pack2(a, a);
            u64 bb = pack2(b, b);
            const ulonglong2* wA = (const ulonglong2*)(cW2 + (2 * kk + 0) * HID + cc * 16);
            const ulonglong2* wB = (const ulonglong2*)(cW2 + (2 * kk + 1) * HID + cc * 16);
            #pragma unroll
            for (int jj = 0; jj < 4; jj++) {
                ulonglong2 wv = wA[jj];
                FMA2(H2[2 * jj + 0], aa, wv.x, H2[2 * jj + 0]);
                FMA2(H2[2 * jj + 1], aa, wv.y, H2[2 * jj + 1]);
            }
            #pragma unroll
            for (int jj = 0; jj < 4; jj++) {
                ulonglong2 wv = wB[jj];
                FMA2(H2[2 * jj + 0], bb, wv.x, H2[2 * jj + 0]);
                FMA2(H2[2 * jj + 1], bb, wv.y, H2[2 * jj + 1]);
            }
        }
        #pragma unroll
        for (int jj = 0; jj < 8; jj++) {
            float a, b; unpack2(H2[jj], a, b);
            a = fmaxf(a, 0.0f); b = fmaxf(b, 0.0f);
            int k0 = cc * 16 + 2 * jj;
            const ulonglong2* w3 = (const ulonglong2*)(cW3 + k0 * 4);
            ulonglong2 wa = w3[0];
            ulonglong2 wb = w3[1];
            u64 aa = pack2(a, a);
            u64 bb = pack2(b, b);
            FMA2(o01, aa, wa.x, o01);
            FMA2(o23, aa, wa.y, o23);
            FMA2(o01, bb, wb.x, o01);
            FMA2(o23, bb, wb.y, o23);
        }
    }
    float o0, o1, o2, o3;
    unpack2(o01, o0, o1);
    unpack2(o23, o2, o3);

    // ---- activations + masked write ----
    if (i0 < n) {
        float c0 = mask ? 1.0f / (1.0f + __expf(-o0)) : 0.0f;
        float c1 = mask ? 1.0f / (1.0f + __expf(-o1)) : 0.0f;
        float c2 = mask ? 1.0f / (1.0f + __expf(-o2)) : 0.0f;
        float sg = mask ? __expf(o3) : 0.0f;
        out[3 * i0 + 0] = c0;
        out[3 * i0 + 1] = c1;
        out[3 * i0 + 2] = c2;
        out[3 * n + i0] = sg;
    }
}

extern "C" void kernel_launch(void* const* d_in, const int* in_sizes, int n_in,
                              void* d_out, int out_size) {
    const float* x   = (const float*)d_in[0];  // [N,3]
    const float* pzh = (const float*)d_in[1];  // [512,512,32]
    const float* phw = (const float*)d_in[2];
    const float* pzw = (const float*)d_in[3];
    const float* W1  = (const float*)d_in[4];  // [32,64]
    const float* W2  = (const float*)d_in[5];  // [64,64]
    const float* W3  = (const float*)d_in[6];  // [64,4]
    float* out = (float*)d_out;

    // Weights -> constant memory (D2D async copies; graph-capturable, no allocs)
    cudaMemcpyToSymbolAsync(cW1, W1, NF * HID  * sizeof(float), 0,
                            cudaMemcpyDeviceToDevice, 0);
    cudaMemcpyToSymbolAsync(cW2, W2, HID * HID * sizeof(float), 0,
                            cudaMemcpyDeviceToDevice, 0);
    cudaMemcpyToSymbolAsync(cW3, W3, HID * 4   * sizeof(float), 0,
                            cudaMemcpyDeviceToDevice, 0);

    int n = in_sizes[0] / 3;
    int blocks = (n + TPB - 1) / TPB;

    size_t smem = (size_t)(8 * 32 * FSTR) * sizeof(float);
    cudaFuncSetAttribute(triplane_decoder_kernel,
                         cudaFuncAttributeMaxDynamicSharedMemorySize, (int)smem);
    triplane_decoder_kernel<<<blocks, TPB, smem>>>(x, pzh, phw, pzw, out, n);
}